// round 6
// baseline (speedup 1.0000x reference)
#include <cuda_runtime.h>
#include <math.h>

// Problem constants (fixed shapes for this problem instance)
#define NMAX 50000
#define EMAX 800000
#define C_IN 64
#define C_HID 64
#define C_OUT 40

// Scratch (allocation-free rule: __device__ globals). 16B-aligned for v4 ops.
__device__ __align__(16) float g_h1[NMAX * C_HID];    // x @ W1
__device__ __align__(16) float g_agg1[NMAX * C_HID];  // aggregated -> relu'd (in place)
__device__ __align__(16) float g_h2[NMAX * C_OUT];    // feat @ W2
__device__ __align__(16) float g_agg2[NMAX * C_OUT];  // aggregated layer 2
__device__ int   g_deg[NMAX];
__device__ float g_dinv[NMAX];

__device__ __forceinline__ void red_add_v4(float* p, float4 v) {
    asm volatile("red.global.add.v4.f32 [%0], {%1,%2,%3,%4};"
                 :: "l"(p), "f"(v.x), "f"(v.y), "f"(v.z), "f"(v.w)
                 : "memory");
}

// ---------------------------------------------------------------------------
// Zero scratch accumulators + degree counters (one grid-stride pass)
// ---------------------------------------------------------------------------
__global__ void zero_kernel(int N) {
    int total = N * C_HID;  // largest buffer
    for (int i = blockIdx.x * blockDim.x + threadIdx.x; i < total;
         i += gridDim.x * blockDim.x) {
        g_agg1[i] = 0.f;
        if (i < N * C_OUT) g_agg2[i] = 0.f;
        if (i < N)         g_deg[i]  = 0;
    }
}

// ---------------------------------------------------------------------------
// Degree of destination nodes (unit weights); self-loop (+1) added in dinv
// ---------------------------------------------------------------------------
__global__ void deg_kernel(const int* __restrict__ ei, int E) {
    int e = blockIdx.x * blockDim.x + threadIdx.x;
    if (e < E) {
        int d = ei[E + e];  // edge_index[1][e]
        atomicAdd(&g_deg[d], 1);
    }
}

__global__ void dinv_kernel(int N) {
    int i = blockIdx.x * blockDim.x + threadIdx.x;
    if (i < N) g_dinv[i] = rsqrtf((float)(g_deg[i] + 1));  // +1 self loop
}

// ---------------------------------------------------------------------------
// Dense GEMM: H[N,COUT] = X[N,CIN] @ W[CIN,COUT].  K = 64 fixed.
// 1 row x 8 cols per thread (2 float4 accumulators) — low register pressure.
// blockDim = (COUT/8, 32); 32-row tiles.
// LAYER1 reads param X -> g_h1, else reads g_agg1 -> g_h2 (as in R2).
// ---------------------------------------------------------------------------
template <int COUT, bool LAYER1>
__global__ void __launch_bounds__(COUT * 4)
gemm_kernel(const float* __restrict__ X, const float* __restrict__ W, int N) {
    constexpr int K = 64;
    constexpr int TROWS = 32;
    __shared__ float Xs[TROWS][K + 1];
    __shared__ float Ws[K * COUT];

    const float* Xin = LAYER1 ? X : g_agg1;
    float* H = LAYER1 ? g_h1 : g_h2;

    const int nthr = COUT * 4;
    const int tid  = threadIdx.y * blockDim.x + threadIdx.x;
    const int row0 = blockIdx.x * TROWS;

    for (int i = tid; i < K * COUT / 4; i += nthr)
        ((float4*)Ws)[i] = ((const float4*)W)[i];

    for (int idx = tid; idx < TROWS * (K / 4); idx += nthr) {
        int r  = idx >> 4;          // 0..31
        int kg = (idx & 15) << 2;   // 0,4,...,60
        float4 v = make_float4(0.f, 0.f, 0.f, 0.f);
        if (row0 + r < N)
            v = *(const float4*)(Xin + (size_t)(row0 + r) * K + kg);
        Xs[r][kg + 0] = v.x;
        Xs[r][kg + 1] = v.y;
        Xs[r][kg + 2] = v.z;
        Xs[r][kg + 3] = v.w;
    }
    __syncthreads();

    const int r  = threadIdx.y;       // 0..31
    const int c0 = threadIdx.x * 8;   // 8-col group
    float4 a0 = make_float4(0.f, 0.f, 0.f, 0.f);
    float4 a1 = make_float4(0.f, 0.f, 0.f, 0.f);
#pragma unroll 8
    for (int k = 0; k < K; k++) {
        float xv = Xs[r][k];
        float4 w0 = *(const float4*)(Ws + k * COUT + c0);
        float4 w1 = *(const float4*)(Ws + k * COUT + c0 + 4);
        a0.x += xv * w0.x; a0.y += xv * w0.y;
        a0.z += xv * w0.z; a0.w += xv * w0.w;
        a1.x += xv * w1.x; a1.y += xv * w1.y;
        a1.z += xv * w1.z; a1.w += xv * w1.w;
    }

    int row = row0 + r;
    if (row < N) {
        *(float4*)(H + (size_t)row * COUT + c0)     = a0;
        *(float4*)(H + (size_t)row * COUT + c0 + 4) = a1;
    }
}

// ---------------------------------------------------------------------------
// Edge scatter: agg[dst] += h[src] * dinv[src]*dinv[dst]
// One thread per (edge, float4 chunk). red.global.add.v4.f32 (no return).
// ---------------------------------------------------------------------------
template <int C, bool LAYER1>
__global__ void scatter_kernel(const int* __restrict__ ei, int E) {
    constexpr int CH = C / 4;
    long long t = (long long)blockIdx.x * blockDim.x + threadIdx.x;
    if (t >= (long long)E * CH) return;
    int e  = (int)(t / CH);
    int ch = (int)(t % CH);

    int s = ei[e];
    int d = ei[E + e];
    float norm = g_dinv[s] * g_dinv[d];

    const float* h = LAYER1 ? g_h1 : g_h2;
    float* agg     = LAYER1 ? g_agg1 : g_agg2;

    float4 v = *(const float4*)(h + (size_t)s * C + ch * 4);
    v.x *= norm; v.y *= norm; v.z *= norm; v.w *= norm;
    red_add_v4(agg + (size_t)d * C + ch * 4, v);
}

// ---------------------------------------------------------------------------
// Layer-1 epilogue: feat = relu(agg1 + h1*dinv^2 + b1)   (in place on agg1)
// ---------------------------------------------------------------------------
__global__ void combine_relu_kernel(const float* __restrict__ b1, int N) {
    int i = blockIdx.x * blockDim.x + threadIdx.x;
    if (i >= N * C_HID) return;
    int n = i / C_HID;
    int c = i - n * C_HID;
    float di = g_dinv[n];
    float v  = g_agg1[i] + g_h1[i] * di * di + b1[c];
    g_agg1[i] = fmaxf(v, 0.f);
}

// ---------------------------------------------------------------------------
// Layer-2 epilogue fused with log_softmax. One warp per node row (C_OUT=40:
// lane handles c=lane and, for lane<8, c=lane+32).
// ---------------------------------------------------------------------------
__global__ void final_kernel(const float* __restrict__ b2,
                             float* __restrict__ out, int N) {
    int gwarp = (blockIdx.x * blockDim.x + threadIdx.x) >> 5;
    int lane  = threadIdx.x & 31;
    if (gwarp >= N) return;

    float di = g_dinv[gwarp];
    float d2 = di * di;
    size_t base = (size_t)gwarp * C_OUT;

    float v0 = g_agg2[base + lane] + g_h2[base + lane] * d2 + b2[lane];
    float v1 = -INFINITY;
    bool has2 = lane < (C_OUT - 32);
    if (has2)
        v1 = g_agg2[base + lane + 32] + g_h2[base + lane + 32] * d2 + b2[lane + 32];

    float m = fmaxf(v0, v1);
#pragma unroll
    for (int o = 16; o; o >>= 1) m = fmaxf(m, __shfl_xor_sync(0xFFFFFFFFu, m, o));

    float s = expf(v0 - m) + (has2 ? expf(v1 - m) : 0.f);
#pragma unroll
    for (int o = 16; o; o >>= 1) s += __shfl_xor_sync(0xFFFFFFFFu, s, o);

    float lg = m + logf(s);
    out[base + lane] = v0 - lg;
    if (has2) out[base + lane + 32] = v1 - lg;
}

// ---------------------------------------------------------------------------
// Launch
// ---------------------------------------------------------------------------
extern "C" void kernel_launch(void* const* d_in, const int* in_sizes, int n_in,
                              void* d_out, int out_size) {
    const float* x  = (const float*)d_in[0];
    const int*   ei = (const int*)d_in[1];   // int32
    const float* W1 = (const float*)d_in[2];
    const float* b1 = (const float*)d_in[3];
    const float* W2 = (const float*)d_in[4];
    const float* b2 = (const float*)d_in[5];
    float* out = (float*)d_out;

    int N = in_sizes[0] / C_IN;
    int E = in_sizes[1] / 2;

    // Zero accumulators + degree
    zero_kernel<<<1024, 256>>>(N);

    // Degree / normalization
    deg_kernel<<<(E + 255) / 256, 256>>>(ei, E);
    dinv_kernel<<<(N + 255) / 256, 256>>>(N);

    // Layer 1: h1 = x @ W1
    gemm_kernel<C_HID, true><<<(N + 31) / 32, dim3(C_HID / 8, 32)>>>(x, W1, N);

    // Scatter edges into agg1
    {
        long long tot = (long long)E * (C_HID / 4);
        scatter_kernel<C_HID, true><<<(unsigned)((tot + 255) / 256), 256>>>(ei, E);
    }

    // agg1 = relu(agg1 + h1*dinv^2 + b1)
    combine_relu_kernel<<<(N * C_HID + 255) / 256, 256>>>(b1, N);

    // Layer 2: h2 = feat @ W2
    gemm_kernel<C_OUT, false><<<(N + 31) / 32, dim3(C_OUT / 8, 32)>>>(nullptr, W2, N);

    // Scatter edges into agg2
    {
        long long tot = (long long)E * (C_OUT / 4);
        scatter_kernel<C_OUT, false><<<(unsigned)((tot + 255) / 256), 256>>>(ei, E);
    }

    // Epilogue + log_softmax
    final_kernel<<<(N + 7) / 8, 256>>>(b2, out, N);
}

// round 7
// speedup vs baseline: 1.8856x; 1.8856x over previous
#include <cuda_runtime.h>
#include <math.h>

#define C_IN  64
#define C_HID 64
#define C_OUT 40
#define NMAX  50000
#define EMAX  800000

// Scratch (allocation-free rule). 16B aligned for float4 ops on MY buffers.
__device__ __align__(16) float g_h1s[NMAX * C_HID];  // (x @ W1) * dinv[row]
__device__ __align__(16) float g_feat[NMAX * C_HID]; // layer-1 output (post relu)
__device__ __align__(16) float g_h2s[NMAX * C_OUT];  // (feat @ W2) * dinv[row]
__device__ int   g_deg[NMAX];
__device__ float g_dinv[NMAX];
__device__ int   g_start[NMAX + 1];  // CSR row offsets (by dst)
__device__ int   g_cursor[NMAX];     // placement cursors
__device__ int   g_csr[EMAX];        // src ids grouped by dst
__device__ int   g_bsum[256];        // scan block sums

// ---------------------------------------------------------------------------
__global__ void zero_deg_kernel(int N) {
    int i = blockIdx.x * blockDim.x + threadIdx.x;
    if (i < N) g_deg[i] = 0;
}

__global__ void deg_kernel(const int* __restrict__ ei, int E) {
    int e = blockIdx.x * blockDim.x + threadIdx.x;
    if (e < E) atomicAdd(&g_deg[ei[E + e]], 1);
}

// ---------------------------------------------------------------------------
// Exclusive scan of g_deg -> g_start. Warp-shuffle based (no big smem arrays).
// scan1: 256 threads scan 512 elements per block; block totals -> g_bsum.
// ---------------------------------------------------------------------------
__global__ void scan1_kernel(int N) {
    __shared__ int warp_sums[8];
    int t    = threadIdx.x;
    int lane = t & 31;
    int wid  = t >> 5;
    int i0   = blockIdx.x * 512 + 2 * t;

    int a = (i0 < N)     ? g_deg[i0]     : 0;
    int b = (i0 + 1 < N) ? g_deg[i0 + 1] : 0;
    int pair = a + b;

    int v = pair;  // inclusive scan of pairs within warp
#pragma unroll
    for (int o = 1; o < 32; o <<= 1) {
        int u = __shfl_up_sync(0xFFFFFFFFu, v, o);
        if (lane >= o) v += u;
    }
    if (lane == 31) warp_sums[wid] = v;
    __syncthreads();
    if (wid == 0) {
        int w = (lane < 8) ? warp_sums[lane] : 0;
#pragma unroll
        for (int o = 1; o < 32; o <<= 1) {
            int u = __shfl_up_sync(0xFFFFFFFFu, w, o);
            if (lane >= o) w += u;
        }
        if (lane < 8) warp_sums[lane] = w;
    }
    __syncthreads();
    int carry = (wid > 0) ? warp_sums[wid - 1] : 0;
    int incl  = v + carry;          // inclusive over block, pair granularity
    int excl  = incl - pair;        // exclusive offset of element i0
    if (i0 < N)     g_start[i0]     = excl;
    if (i0 + 1 < N) g_start[i0 + 1] = excl + a;
    if (t == 255)   g_bsum[blockIdx.x] = incl;  // block total
}

// scan2: one block (128 threads) turns block totals into exclusive offsets.
__global__ void scan2_kernel(int nb) {
    __shared__ int ws[4];
    int t    = threadIdx.x;  // 0..127
    int lane = t & 31;
    int wid  = t >> 5;
    int orig = (t < nb) ? g_bsum[t] : 0;
    int v = orig;
#pragma unroll
    for (int o = 1; o < 32; o <<= 1) {
        int u = __shfl_up_sync(0xFFFFFFFFu, v, o);
        if (lane >= o) v += u;
    }
    if (lane == 31) ws[wid] = v;
    __syncthreads();
    if (wid == 0) {
        int w = (lane < 4) ? ws[lane] : 0;
#pragma unroll
        for (int o = 1; o < 32; o <<= 1) {
            int u = __shfl_up_sync(0xFFFFFFFFu, w, o);
            if (lane >= o) w += u;
        }
        if (lane < 4) ws[lane] = w;
    }
    __syncthreads();
    int carry = (wid > 0) ? ws[wid - 1] : 0;
    if (t < nb) g_bsum[t] = v + carry - orig;  // exclusive
}

__global__ void scan3_kernel(int N, int E) {
    int i = blockIdx.x * blockDim.x + threadIdx.x;
    if (i < N) {
        int v = g_start[i] + g_bsum[i >> 9];
        g_start[i]  = v;
        g_cursor[i] = v;
        g_dinv[i]   = rsqrtf((float)(g_deg[i] + 1));  // +1 self loop
        if (i == 0) g_start[N] = E;
    }
}

__global__ void fill_csr_kernel(const int* __restrict__ ei, int E) {
    int e = blockIdx.x * blockDim.x + threadIdx.x;
    if (e < E) {
        int s = ei[e];
        int d = ei[E + e];
        int p = atomicAdd(&g_cursor[d], 1);
        g_csr[p] = s;
    }
}

// ---------------------------------------------------------------------------
// Dense GEMM (R2-proven shape): H[r,:] = (X[r,:] @ W) * dinv[r].  K=64.
// Thread-per-output-column, W + 64-row X tile in smem.
// LAYER1: X param -> g_h1s ; else: g_feat -> g_h2s.
// ---------------------------------------------------------------------------
template <int CIN, int COUT, bool LAYER1>
__global__ void gemm_kernel(const float* __restrict__ X,
                            const float* __restrict__ W, int N) {
    constexpr int ROWS = 64;
    __shared__ float Ws[CIN * COUT];
    __shared__ float Xs[ROWS * CIN];

    const float* Xin = LAYER1 ? X : g_feat;
    float* H = LAYER1 ? g_h1s : g_h2s;

    int tid  = threadIdx.y * COUT + threadIdx.x;
    int nthr = blockDim.x * blockDim.y;

    for (int i = tid; i < CIN * COUT; i += nthr) Ws[i] = W[i];

    int row0  = blockIdx.x * ROWS;
    int nrows = min(ROWS, N - row0);
    for (int i = tid; i < nrows * CIN; i += nthr) Xs[i] = Xin[(size_t)row0 * CIN + i];
    __syncthreads();

    int c = threadIdx.x;
    for (int r = threadIdx.y; r < nrows; r += blockDim.y) {
        float acc = 0.f;
#pragma unroll
        for (int k = 0; k < CIN; k++) acc += Xs[r * CIN + k] * Ws[k * COUT + c];
        H[(size_t)(row0 + r) * COUT + c] = acc * g_dinv[row0 + r];
    }
}

// ---------------------------------------------------------------------------
// Layer-1 aggregate: feat[d] = relu(dinv[d]*(h1s[d] + sum_{src->d} h1s[src]) + b1)
// Half-warp (16 lanes x float4 = 64 ch) per node; 2 nodes/warp.
// ---------------------------------------------------------------------------
__global__ void agg1_kernel(const float* __restrict__ b1, int N) {
    int lane = threadIdx.x & 31;
    int warp = (blockIdx.x * blockDim.x + threadIdx.x) >> 5;
    int node = warp * 2 + (lane >> 4);
    if (node >= N) return;
    int sub = lane & 15;

    const float4* hs = (const float4*)g_h1s;  // row stride 16 float4
    float4 acc = hs[node * 16 + sub];         // self loop
    int i = g_start[node], end = g_start[node + 1];
#pragma unroll 4
    for (; i < end; i++) {
        float4 a = hs[g_csr[i] * 16 + sub];
        acc.x += a.x; acc.y += a.y; acc.z += a.z; acc.w += a.w;
    }
    float di = g_dinv[node];
    int c = sub * 4;  // scalar bias loads (harness ptr alignment unknown)
    float4 o;
    o.x = fmaxf(fmaf(acc.x, di, b1[c + 0]), 0.f);
    o.y = fmaxf(fmaf(acc.y, di, b1[c + 1]), 0.f);
    o.z = fmaxf(fmaf(acc.z, di, b1[c + 2]), 0.f);
    o.w = fmaxf(fmaf(acc.w, di, b1[c + 3]), 0.f);
    ((float4*)g_feat)[node * 16 + sub] = o;
}

// ---------------------------------------------------------------------------
// Layer-2 aggregate + bias + log_softmax.  C_OUT=40 = 10 float4 chunks.
// Half-warp per node; lanes sub<10 carry data, all lanes join shuffles.
// ---------------------------------------------------------------------------
__global__ void agg2_kernel(const float* __restrict__ b2,
                            float* __restrict__ out, int N) {
    int lane = threadIdx.x & 31;
    int warp = (blockIdx.x * blockDim.x + threadIdx.x) >> 5;
    int node = warp * 2 + (lane >> 4);
    int sub  = lane & 15;
    bool valid = (node < N) && (sub < 10);
    int nc = (node < N) ? node : 0;

    float4 v = make_float4(-INFINITY, -INFINITY, -INFINITY, -INFINITY);
    if (valid) {
        const float4* hs = (const float4*)g_h2s;  // row stride 10 float4
        float4 acc = hs[nc * 10 + sub];           // self loop
        int i = g_start[nc], end = g_start[nc + 1];
#pragma unroll 4
        for (; i < end; i++) {
            float4 a = hs[g_csr[i] * 10 + sub];
            acc.x += a.x; acc.y += a.y; acc.z += a.z; acc.w += a.w;
        }
        float di = g_dinv[nc];
        int c = sub * 4;  // scalar bias loads
        v = make_float4(fmaf(acc.x, di, b2[c + 0]),
                        fmaf(acc.y, di, b2[c + 1]),
                        fmaf(acc.z, di, b2[c + 2]),
                        fmaf(acc.w, di, b2[c + 3]));
    }

    // reductions stay within each 16-lane half (offsets < 16)
    float m = fmaxf(fmaxf(v.x, v.y), fmaxf(v.z, v.w));
#pragma unroll
    for (int o = 8; o; o >>= 1) m = fmaxf(m, __shfl_xor_sync(0xFFFFFFFFu, m, o));

    float s = valid ? (expf(v.x - m) + expf(v.y - m) + expf(v.z - m) + expf(v.w - m))
                    : 0.f;
#pragma unroll
    for (int o = 8; o; o >>= 1) s += __shfl_xor_sync(0xFFFFFFFFu, s, o);

    float lg = m + logf(s);
    if (valid) {
        float4 o4 = make_float4(v.x - lg, v.y - lg, v.z - lg, v.w - lg);
        ((float4*)out)[nc * 10 + sub] = o4;  // out rows = 160B, 16B-aligned
    }
}

// ---------------------------------------------------------------------------
extern "C" void kernel_launch(void* const* d_in, const int* in_sizes, int n_in,
                              void* d_out, int out_size) {
    const float* x  = (const float*)d_in[0];
    const int*   ei = (const int*)d_in[1];
    const float* W1 = (const float*)d_in[2];
    const float* b1 = (const float*)d_in[3];
    const float* W2 = (const float*)d_in[4];
    const float* b2 = (const float*)d_in[5];
    float* out = (float*)d_out;

    int N  = in_sizes[0] / C_IN;
    int E  = in_sizes[1] / 2;
    int nb = (N + 511) / 512;

    // Degree + normalization + CSR build
    zero_deg_kernel<<<(N + 255) / 256, 256>>>(N);
    deg_kernel<<<(E + 255) / 256, 256>>>(ei, E);
    scan1_kernel<<<nb, 256>>>(N);
    scan2_kernel<<<1, 128>>>(nb);
    scan3_kernel<<<(N + 255) / 256, 256>>>(N, E);
    fill_csr_kernel<<<(E + 255) / 256, 256>>>(ei, E);

    // Layer 1
    gemm_kernel<C_IN, C_HID, true><<<(N + 63) / 64, dim3(C_HID, 4)>>>(x, W1, N);
    agg1_kernel<<<(N + 15) / 16, 256>>>(b1, N);

    // Layer 2
    gemm_kernel<C_HID, C_OUT, false><<<(N + 63) / 64, dim3(C_OUT, 6)>>>(nullptr, W2, N);
    agg2_kernel<<<(N + 15) / 16, 256>>>(b2, out, N);
}